// round 11
// baseline (speedup 1.0000x reference)
#include <cuda_runtime.h>
#include <math.h>
#include <stdint.h>

// Problem constants
#define D_MODEL 1024
#define NH      16
#define DK_     64
#define MROWS   4096      // B*L = 2*2048
#define DFF_    4096
#define SEQL    2048

// ---------------------------------------------------------------------------
// Scratch (static device globals; no allocations allowed)
// ---------------------------------------------------------------------------
__device__ float g_q   [MROWS * D_MODEL];
__device__ float g_k   [MROWS * D_MODEL];
__device__ float g_v   [MROWS * D_MODEL];
__device__ float g_ctx [MROWS * D_MODEL];
__device__ float g_proj[MROWS * D_MODEL];
__device__ float g_x1  [MROWS * D_MODEL];
__device__ float g_x2  [MROWS * D_MODEL];
__device__ float g_ff  [MROWS * DFF_];

__device__ __forceinline__ float gelu_exact(float x) {
    return 0.5f * x * (1.0f + erff(x * 0.70710678118654752f));
}

__device__ __forceinline__ float to_tf32(float x) {
    uint32_t u;
    asm volatile("cvt.rna.tf32.f32 %0, %1;" : "=r"(u) : "f"(x));
    return __uint_as_float(u);
}
__device__ __forceinline__ uint32_t to_tf32_bits(float x) {
    uint32_t u;
    asm volatile("cvt.rna.tf32.f32 %0, %1;" : "=r"(u) : "f"(x));
    return u;
}

__device__ __forceinline__ void mma_tf32(float* c, const uint32_t* a, const uint32_t* b) {
    asm volatile(
        "mma.sync.aligned.m16n8k8.row.col.f32.tf32.tf32.f32 "
        "{%0,%1,%2,%3}, {%4,%5,%6,%7}, {%8,%9}, {%0,%1,%2,%3};\n"
        : "+f"(c[0]), "+f"(c[1]), "+f"(c[2]), "+f"(c[3])
        : "r"(a[0]), "r"(a[1]), "r"(a[2]), "r"(a[3]), "r"(b[0]), "r"(b[1]));
}

// cp.async helpers
__device__ __forceinline__ void cp_async16(void* smem, const void* gmem) {
    uint32_t s = (uint32_t)__cvta_generic_to_shared(smem);
    asm volatile("cp.async.cg.shared.global [%0], [%1], 16;\n" :: "r"(s), "l"(gmem));
}
__device__ __forceinline__ void cp_commit() {
    asm volatile("cp.async.commit_group;\n" ::: "memory");
}
template<int N>
__device__ __forceinline__ void cp_wait() {
    asm volatile("cp.async.wait_group %0;\n" :: "n"(N) : "memory");
}

// ---------------------------------------------------------------------------
// TF32 tensor-core GEMM: CTA tile 128x256, 8 warps (2x4... actually 1x... )
// warp layout: wm = wid>>2 (0..1) rows of 64, wn = wid&3 (0..3) cols of 64.
// Warp tile 64x64 => per k-tile: 16 A-LDS + 16 B-LDS for 32 mma (ratio 1.0).
// GBK=8, 3-stage cp.async, wait<1>, 2 barriers/k-tile (R4-measured pipeline).
// Dynamic smem (56 KB). 1 CTA/SM (reg-bound).
// C[M,N] = A[M,K] @ B[K,N] + bias, ACT 0=none 1=gelu.
// ---------------------------------------------------------------------------
#define GBM 128
#define GBN 256
#define GBK 8
#define APAD 20
#define BSTR 264          // 256 + 8 pad (8 mod 32 => bank = 8*lc+lr, distinct)
#define STAGES 3
#define GEMM_SMEM (STAGES * GBM * APAD * 4 + STAGES * GBK * BSTR * 4)  // 56064

template<int ACT>
__global__ __launch_bounds__(256, 1)
void gemm_tf32(const float* __restrict__ A, const float* __restrict__ B,
               const float* __restrict__ bias, float* __restrict__ C,
               int M, int N, int K)
{
    extern __shared__ float smem[];
    float (*As)[GBM][APAD] = (float (*)[GBM][APAD])smem;
    float (*Bs)[GBK][BSTR] = (float (*)[GBK][BSTR])(smem + STAGES * GBM * APAD);

    const int t    = threadIdx.x;
    const int wid  = t >> 5;
    const int lane = t & 31;
    const int wm   = wid >> 2;        // 0..1 (row of 64)
    const int wn   = wid & 3;         // 0..3 (col of 64)
    const int lr   = lane >> 2;       // 0..7
    const int lc   = lane & 3;        // 0..3

    const int m0 = blockIdx.y * GBM;
    const int n0 = blockIdx.x * GBN;

    // cp.async mapping:
    // A tile 128x8 floats: 256 chunks of 16B, 1/thread
    const int arow = t >> 1;          // 0..127
    const int acol = (t & 1) * 4;     // 0 or 4
    // B tile 8x256 floats: 512 chunks, 2/thread: chunk c = t and t+256
    const int brow0 = t >> 6;         // 0..3
    const int bcol  = (t & 63) * 4;   // 0..252

    const float* Ag  = A + (size_t)(m0 + arow) * K + acol;
    const float* Bg0 = B + (size_t)brow0 * N + n0 + bcol;
    const float* Bg1 = B + (size_t)(brow0 + 4) * N + n0 + bcol;

    float acc[4][8][4];
#pragma unroll
    for (int i = 0; i < 4; i++)
#pragma unroll
        for (int j = 0; j < 8; j++)
#pragma unroll
            for (int r = 0; r < 4; r++) acc[i][j][r] = 0.0f;

    const int kTiles = K / GBK;

    // Prologue: stages 0 and 1 in flight
#pragma unroll
    for (int s = 0; s < 2; s++) {
        cp_async16(&As[s][arow][acol],      Ag  + (size_t)s * GBK);
        cp_async16(&Bs[s][brow0][bcol],     Bg0 + (size_t)s * GBK * N);
        cp_async16(&Bs[s][brow0 + 4][bcol], Bg1 + (size_t)s * GBK * N);
        cp_commit();
    }

    int p = 0;
    for (int kt = 0; kt < kTiles; kt++) {
        cp_wait<1>();
        __syncthreads();

        // ---- compute stage p (K=8): 32 mma per warp ----
        uint32_t afr[4][4];
        uint32_t bfr[8][2];
#pragma unroll
        for (int mf = 0; mf < 4; mf++) {
            const int m = wm * 64 + mf * 16 + lr;
            afr[mf][0] = __float_as_uint(As[p][m    ][lc]);
            afr[mf][1] = __float_as_uint(As[p][m + 8][lc]);
            afr[mf][2] = __float_as_uint(As[p][m    ][lc + 4]);
            afr[mf][3] = __float_as_uint(As[p][m + 8][lc + 4]);
        }
#pragma unroll
        for (int nf = 0; nf < 8; nf++) {
            const int n = wn * 64 + nf * 8 + lr;
            bfr[nf][0] = __float_as_uint(Bs[p][lc    ][n]);
            bfr[nf][1] = __float_as_uint(Bs[p][lc + 4][n]);
        }
#pragma unroll
        for (int mf = 0; mf < 4; mf++)
#pragma unroll
            for (int nf = 0; nf < 8; nf++)
                mma_tf32(acc[mf][nf], afr[mf], bfr[nf]);

        // ---- issue stage kt+2 ----
        if (kt + 2 < kTiles) {
            const int s = (p + 2) % STAGES;
            const size_t ko = (size_t)(kt + 2) * GBK;
            cp_async16(&As[s][arow][acol],      Ag  + ko);
            cp_async16(&Bs[s][brow0][bcol],     Bg0 + ko * N);
            cp_async16(&Bs[s][brow0 + 4][bcol], Bg1 + ko * N);
        }
        cp_commit();

        p = (p + 1) % STAGES;
        __syncthreads();
    }

    // Epilogue
#pragma unroll
    for (int mf = 0; mf < 4; mf++) {
        const int r0 = m0 + wm * 64 + mf * 16 + lr;
#pragma unroll
        for (int nf = 0; nf < 8; nf++) {
            const int c0 = n0 + wn * 64 + nf * 8 + 2 * lc;
            const float b0 = bias[c0], b1 = bias[c0 + 1];
            float v0 = acc[mf][nf][0] + b0;
            float v1 = acc[mf][nf][1] + b1;
            float v2 = acc[mf][nf][2] + b0;
            float v3 = acc[mf][nf][3] + b1;
            if (ACT == 1) {
                v0 = gelu_exact(v0); v1 = gelu_exact(v1);
                v2 = gelu_exact(v2); v3 = gelu_exact(v3);
            }
            *(float2*)(C + (size_t)r0 * N + c0)       = make_float2(v0, v1);
            *(float2*)(C + (size_t)(r0 + 8) * N + c0) = make_float2(v2, v3);
        }
    }
}

// ---------------------------------------------------------------------------
// Tensor-core flash attention (TF32 mma), DK=64 — unchanged (measured best)
// ---------------------------------------------------------------------------
#define KS_STRIDE 68
#define VS_STRIDE 72

template<bool CAUSAL>
__global__ __launch_bounds__(256)
void flash_attn_tc(const float* __restrict__ Q, const float* __restrict__ K,
                   const float* __restrict__ V, float* __restrict__ O, int L)
{
    __shared__ float Ks[64][KS_STRIDE];
    __shared__ float Vs[64][VS_STRIDE];

    const int t    = threadIdx.x;
    const int lane = t & 31;
    const int w    = t >> 5;
    const int lr   = lane >> 2;
    const int lc   = lane & 3;

    const int qt = blockIdx.x;
    const int bh = blockIdx.y;
    const int b  = bh >> 4;
    const int h  = bh & 15;
    const int q0 = qt * 128;
    const int wrow = q0 + w * 16;

    const float* Qb = Q + (size_t)(b * L) * D_MODEL + h * DK_;
    const float* Kb = K + (size_t)(b * L) * D_MODEL + h * DK_;
    const float* Vb = V + (size_t)(b * L) * D_MODEL + h * DK_;

    uint32_t qf[8][4];
    {
        const float* qr0 = Qb + (size_t)(wrow + lr) * D_MODEL;
        const float* qr1 = Qb + (size_t)(wrow + lr + 8) * D_MODEL;
#pragma unroll
        for (int kc = 0; kc < 8; kc++) {
            qf[kc][0] = to_tf32_bits(0.125f * qr0[8 * kc + lc]);
            qf[kc][1] = to_tf32_bits(0.125f * qr1[8 * kc + lc]);
            qf[kc][2] = to_tf32_bits(0.125f * qr0[8 * kc + lc + 4]);
            qf[kc][3] = to_tf32_bits(0.125f * qr1[8 * kc + lc + 4]);
        }
    }

    float o[8][4];
#pragma unroll
    for (int nf = 0; nf < 8; nf++)
#pragma unroll
        for (int i = 0; i < 4; i++) o[nf][i] = 0.0f;
    float m0r = -1e30f, m1r = -1e30f;
    float l0r = 0.0f,  l1r = 0.0f;

    const int ntile = CAUSAL ? (2 * qt + 2) : (L >> 6);

    for (int kt = 0; kt < ntile; kt++) {
        const int k0 = kt * 64;
        __syncthreads();
#pragma unroll
        for (int i = 0; i < 4; i++) {
            const int idx = i * 256 + t;
            const int row = idx >> 4;
            const int c4  = (idx & 15) * 4;
            const size_t g = (size_t)(k0 + row) * D_MODEL + c4;
            float4 kv = *(const float4*)(Kb + g);
            float4 vv = *(const float4*)(Vb + g);
            float4 s;
            s.x = to_tf32(kv.x); s.y = to_tf32(kv.y); s.z = to_tf32(kv.z); s.w = to_tf32(kv.w);
            *(float4*)&Ks[row][c4] = s;
            s.x = to_tf32(vv.x); s.y = to_tf32(vv.y); s.z = to_tf32(vv.z); s.w = to_tf32(vv.w);
            *(float4*)&Vs[row][c4] = s;
        }
        __syncthreads();

        const bool active = (!CAUSAL) || (k0 <= wrow + 15);
        if (active) {
            float sacc[8][4];
#pragma unroll
            for (int nf = 0; nf < 8; nf++) {
                sacc[nf][0] = sacc[nf][1] = sacc[nf][2] = sacc[nf][3] = 0.0f;
#pragma unroll
                for (int kc = 0; kc < 8; kc++) {
                    uint32_t bfr[2];
                    bfr[0] = __float_as_uint(Ks[8 * nf + lr][8 * kc + lc]);
                    bfr[1] = __float_as_uint(Ks[8 * nf + lr][8 * kc + lc + 4]);
                    mma_tf32(sacc[nf], qf[kc], bfr);
                }
            }

            if (CAUSAL && (k0 + 63 > wrow)) {
                const int r0 = wrow + lr, r1 = wrow + lr + 8;
#pragma unroll
                for (int nf = 0; nf < 8; nf++) {
                    const int key = k0 + 8 * nf + 2 * lc;
                    if (key     > r0) sacc[nf][0] = -1e30f;
                    if (key + 1 > r0) sacc[nf][1] = -1e30f;
                    if (key     > r1) sacc[nf][2] = -1e30f;
                    if (key + 1 > r1) sacc[nf][3] = -1e30f;
                }
            }

            float mx0 = -1e30f, mx1 = -1e30f;
#pragma unroll
            for (int nf = 0; nf < 8; nf++) {
                mx0 = fmaxf(mx0, fmaxf(sacc[nf][0], sacc[nf][1]));
                mx1 = fmaxf(mx1, fmaxf(sacc[nf][2], sacc[nf][3]));
            }
            mx0 = fmaxf(mx0, __shfl_xor_sync(0xffffffffu, mx0, 1));
            mx0 = fmaxf(mx0, __shfl_xor_sync(0xffffffffu, mx0, 2));
            mx1 = fmaxf(mx1, __shfl_xor_sync(0xffffffffu, mx1, 1));
            mx1 = fmaxf(mx1, __shfl_xor_sync(0xffffffffu, mx1, 2));

            const float nm0 = fmaxf(m0r, mx0);
            const float nm1 = fmaxf(m1r, mx1);
            const float cr0 = __expf(m0r - nm0);
            const float cr1 = __expf(m1r - nm1);
            float sum0 = 0.f, sum1 = 0.f;
#pragma unroll
            for (int nf = 0; nf < 8; nf++) {
                sacc[nf][0] = __expf(sacc[nf][0] - nm0);
                sacc[nf][1] = __expf(sacc[nf][1] - nm0);
                sacc[nf][2] = __expf(sacc[nf][2] - nm1);
                sacc[nf][3] = __expf(sacc[nf][3] - nm1);
                sum0 += sacc[nf][0] + sacc[nf][1];
                sum1 += sacc[nf][2] + sacc[nf][3];
            }
            sum0 += __shfl_xor_sync(0xffffffffu, sum0, 1);
            sum0 += __shfl_xor_sync(0xffffffffu, sum0, 2);
            sum1 += __shfl_xor_sync(0xffffffffu, sum1, 1);
            sum1 += __shfl_xor_sync(0xffffffffu, sum1, 2);

            l0r = l0r * cr0 + sum0;
            l1r = l1r * cr1 + sum1;
            m0r = nm0; m1r = nm1;
#pragma unroll
            for (int nf = 0; nf < 8; nf++) {
                o[nf][0] *= cr0; o[nf][1] *= cr0;
                o[nf][2] *= cr1; o[nf][3] *= cr1;
            }

            const int qbase = lane & ~3;
            const int srcA  = qbase | (lc >> 1);
            const int srcB  = srcA + 2;
#pragma unroll
            for (int kc = 0; kc < 8; kc++) {
                const float p0a = __shfl_sync(0xffffffffu, sacc[kc][0], srcA);
                const float p1a = __shfl_sync(0xffffffffu, sacc[kc][1], srcA);
                const float p2a = __shfl_sync(0xffffffffu, sacc[kc][2], srcA);
                const float p3a = __shfl_sync(0xffffffffu, sacc[kc][3], srcA);
                const float p0b = __shfl_sync(0xffffffffu, sacc[kc][0], srcB);
                const float p1b = __shfl_sync(0xffffffffu, sacc[kc][1], srcB);
                const float p2b = __shfl_sync(0xffffffffu, sacc[kc][2], srcB);
                const float p3b = __shfl_sync(0xffffffffu, sacc[kc][3], srcB);
                uint32_t af[4];
                const bool odd = (lc & 1);
                af[0] = __float_as_uint(odd ? p1a : p0a);
                af[1] = __float_as_uint(odd ? p3a : p2a);
                af[2] = __float_as_uint(odd ? p1b : p0b);
                af[3] = __float_as_uint(odd ? p3b : p2b);
#pragma unroll
                for (int nf = 0; nf < 8; nf++) {
                    uint32_t bfr[2];
                    bfr[0] = __float_as_uint(Vs[8 * kc + lc    ][8 * nf + lr]);
                    bfr[1] = __float_as_uint(Vs[8 * kc + lc + 4][8 * nf + lr]);
                    mma_tf32(o[nf], af, bfr);
                }
            }
        }
    }

    const float inv0 = 1.0f / l0r;
    const float inv1 = 1.0f / l1r;
    float* O0 = O + (size_t)(b * L + wrow + lr) * D_MODEL + h * DK_;
    float* O1 = O + (size_t)(b * L + wrow + lr + 8) * D_MODEL + h * DK_;
#pragma unroll
    for (int nf = 0; nf < 8; nf++) {
        const int c = 8 * nf + 2 * lc;
        *(float2*)(O0 + c) = make_float2(o[nf][0] * inv0, o[nf][1] * inv0);
        *(float2*)(O1 + c) = make_float2(o[nf][2] * inv1, o[nf][3] * inv1);
    }
}

// ---------------------------------------------------------------------------
// Fused residual add + LayerNorm over last dim (1024). 1 block / row.
// ---------------------------------------------------------------------------
__global__ __launch_bounds__(128)
void add_layernorm(const float* __restrict__ A, const float* __restrict__ Bb,
                   const float* __restrict__ g, const float* __restrict__ be,
                   float* __restrict__ out)
{
    const int row = blockIdx.x;
    const int t = threadIdx.x;
    const float* a = A  + (size_t)row * D_MODEL;
    const float* b = Bb + (size_t)row * D_MODEL;

    float v[8];
    float s = 0.f, sq = 0.f;
#pragma unroll
    for (int i = 0; i < 8; i++) {
        const int c = t + i * 128;
        v[i] = a[c] + b[c];
        s += v[i];
        sq = fmaf(v[i], v[i], sq);
    }
#pragma unroll
    for (int o = 16; o > 0; o >>= 1) {
        s  += __shfl_down_sync(0xffffffffu, s,  o);
        sq += __shfl_down_sync(0xffffffffu, sq, o);
    }
    __shared__ float rs[4], rq[4];
    __shared__ float mean_s, rstd_s;
    const int w = t >> 5, ln = t & 31;
    if (ln == 0) { rs[w] = s; rq[w] = sq; }
    __syncthreads();
    if (t == 0) {
        const float S  = rs[0] + rs[1] + rs[2] + rs[3];
        const float Q2 = rq[0] + rq[1] + rq[2] + rq[3];
        const float mean = S * (1.0f / 1024.0f);
        const float var  = Q2 * (1.0f / 1024.0f) - mean * mean;
        mean_s = mean;
        rstd_s = rsqrtf(var + 1e-5f);
    }
    __syncthreads();
    const float mean = mean_s, rstd = rstd_s;
    float* op = out + (size_t)row * D_MODEL;
#pragma unroll
    for (int i = 0; i < 8; i++) {
        const int c = t + i * 128;
        op[c] = (v[i] - mean) * rstd * g[c] + be[c];
    }
}

// ---------------------------------------------------------------------------
// Host launcher
// ---------------------------------------------------------------------------
static float* devptr(const void* sym) {
    void* p = nullptr;
    cudaGetSymbolAddress(&p, sym);
    return (float*)p;
}

extern "C" void kernel_launch(void* const* d_in, const int* in_sizes, int n_in,
                              void* d_out, int out_size)
{
    const float* x   = (const float*)d_in[0];
    const float* enc = (const float*)d_in[1];
    const float* swq = (const float*)d_in[4];
    const float* sbq = (const float*)d_in[5];
    const float* swk = (const float*)d_in[6];
    const float* sbk = (const float*)d_in[7];
    const float* swv = (const float*)d_in[8];
    const float* sbv = (const float*)d_in[9];
    const float* swo = (const float*)d_in[10];
    const float* sbo = (const float*)d_in[11];
    const float* cwq = (const float*)d_in[12];
    const float* cbq = (const float*)d_in[13];
    const float* cwk = (const float*)d_in[14];
    const float* cbk = (const float*)d_in[15];
    const float* cwv = (const float*)d_in[16];
    const float* cbv = (const float*)d_in[17];
    const float* cwo = (const float*)d_in[18];
    const float* cbo = (const float*)d_in[19];
    const float* fw1 = (const float*)d_in[20];
    const float* fb1 = (const float*)d_in[21];
    const float* fw2 = (const float*)d_in[22];
    const float* fb2 = (const float*)d_in[23];
    const float* n1g = (const float*)d_in[24];
    const float* n1b = (const float*)d_in[25];
    const float* n2g = (const float*)d_in[26];
    const float* n2b = (const float*)d_in[27];
    const float* n3g = (const float*)d_in[28];
    const float* n3b = (const float*)d_in[29];
    float* out = (float*)d_out;

    float* q    = devptr(g_q);
    float* k    = devptr(g_k);
    float* v    = devptr(g_v);
    float* ctx  = devptr(g_ctx);
    float* proj = devptr(g_proj);
    float* x1   = devptr(g_x1);
    float* x2   = devptr(g_x2);
    float* ff   = devptr(g_ff);

    static bool attr_done = false;
    if (!attr_done) {
        cudaFuncSetAttribute(gemm_tf32<0>, cudaFuncAttributeMaxDynamicSharedMemorySize, GEMM_SMEM);
        cudaFuncSetAttribute(gemm_tf32<1>, cudaFuncAttributeMaxDynamicSharedMemorySize, GEMM_SMEM);
        attr_done = true;
    }

    const int M = MROWS, Dm = D_MODEL, Dff = DFF_;
    dim3 blk(256);
    dim3 gP (Dm  / GBN, M / GBM);   // (4, 32)  projections
    dim3 gF1(Dff / GBN, M / GBM);   // (16, 32) FFN up
    dim3 gA (SEQL / 128, 32);       // (16, B*H)

    // ---- self attention ----
    gemm_tf32<0><<<gP, blk, GEMM_SMEM>>>(x, swq, sbq, q, M, Dm, Dm);
    gemm_tf32<0><<<gP, blk, GEMM_SMEM>>>(x, swk, sbk, k, M, Dm, Dm);
    gemm_tf32<0><<<gP, blk, GEMM_SMEM>>>(x, swv, sbv, v, M, Dm, Dm);
    flash_attn_tc<true><<<gA, 256>>>(q, k, v, ctx, SEQL);
    gemm_tf32<0><<<gP, blk, GEMM_SMEM>>>(ctx, swo, sbo, proj, M, Dm, Dm);
    add_layernorm<<<M, 128>>>(x, proj, n1g, n1b, x1);

    // ---- cross attention ----
    gemm_tf32<0><<<gP, blk, GEMM_SMEM>>>(x1,  cwq, cbq, q, M, Dm, Dm);
    gemm_tf32<0><<<gP, blk, GEMM_SMEM>>>(enc, cwk, cbk, k, M, Dm, Dm);
    gemm_tf32<0><<<gP, blk, GEMM_SMEM>>>(enc, cwv, cbv, v, M, Dm, Dm);
    flash_attn_tc<false><<<gA, 256>>>(q, k, v, ctx, SEQL);
    gemm_tf32<0><<<gP, blk, GEMM_SMEM>>>(ctx, cwo, cbo, proj, M, Dm, Dm);
    add_layernorm<<<M, 128>>>(x1, proj, n2g, n2b, x2);

    // ---- feed-forward ----
    gemm_tf32<1><<<gF1, blk, GEMM_SMEM>>>(x2, fw1, fb1, ff, M, Dff, Dm);
    gemm_tf32<0><<<gP,  blk, GEMM_SMEM>>>(ff, fw2, fb2, proj, M, Dm, Dff);
    add_layernorm<<<M, 128>>>(x2, proj, n3g, n3b, out);
}

// round 12
// speedup vs baseline: 1.1594x; 1.1594x over previous
#include <cuda_runtime.h>
#include <math.h>
#include <stdint.h>

// Problem constants
#define D_MODEL 1024
#define NH      16
#define DK_     64
#define MROWS   4096      // B*L = 2*2048
#define DFF_    4096
#define SEQL    2048

// ---------------------------------------------------------------------------
// Scratch (static device globals; no allocations allowed)
// ---------------------------------------------------------------------------
__device__ float g_q   [MROWS * D_MODEL];
__device__ float g_k   [MROWS * D_MODEL];
__device__ float g_v   [MROWS * D_MODEL];
__device__ float g_ctx [MROWS * D_MODEL];
__device__ float g_proj[MROWS * D_MODEL];
__device__ float g_x1  [MROWS * D_MODEL];
__device__ float g_x2  [MROWS * D_MODEL];
__device__ float g_ff  [MROWS * DFF_];

__device__ __forceinline__ float gelu_exact(float x) {
    return 0.5f * x * (1.0f + erff(x * 0.70710678118654752f));
}

__device__ __forceinline__ uint32_t to_tf32_bits(float x) {
    uint32_t u;
    asm volatile("cvt.rna.tf32.f32 %0, %1;" : "=r"(u) : "f"(x));
    return u;
}

__device__ __forceinline__ void mma_tf32(float* c, const uint32_t* a, const uint32_t* b) {
    asm volatile(
        "mma.sync.aligned.m16n8k8.row.col.f32.tf32.tf32.f32 "
        "{%0,%1,%2,%3}, {%4,%5,%6,%7}, {%8,%9}, {%0,%1,%2,%3};\n"
        : "+f"(c[0]), "+f"(c[1]), "+f"(c[2]), "+f"(c[3])
        : "r"(a[0]), "r"(a[1]), "r"(a[2]), "r"(a[3]), "r"(b[0]), "r"(b[1]));
}

// cp.async helpers
__device__ __forceinline__ void cp_async16(void* smem, const void* gmem) {
    uint32_t s = (uint32_t)__cvta_generic_to_shared(smem);
    asm volatile("cp.async.cg.shared.global [%0], [%1], 16;\n" :: "r"(s), "l"(gmem));
}
__device__ __forceinline__ void cp_commit() {
    asm volatile("cp.async.commit_group;\n" ::: "memory");
}
template<int N>
__device__ __forceinline__ void cp_wait() {
    asm volatile("cp.async.wait_group %0;\n" :: "n"(N) : "memory");
}

// ---------------------------------------------------------------------------
// TF32 tensor-core GEMM, cp.async 3-stage pipeline, GBK=8 — R4 EXACT
// (best measured: 1646.6 us total). C = A@B + bias, ACT 0=none 1=gelu.
// ---------------------------------------------------------------------------
#define GBM 128
#define GBN 128
#define GBK 8
#define APAD 20
#define BPAD 136
#define STAGES 3

template<int ACT>
__global__ __launch_bounds__(256, 2)
void gemm_tf32(const float* __restrict__ A, const float* __restrict__ B,
               const float* __restrict__ bias, float* __restrict__ C,
               int M, int N, int K)
{
    __shared__ float As[STAGES][GBM][APAD];   // 30720 B
    __shared__ float Bs[STAGES][GBK][BPAD];   // 13056 B

    const int t    = threadIdx.x;
    const int wid  = t >> 5;
    const int lane = t & 31;
    const int wm   = wid >> 2;
    const int wn   = wid & 3;
    const int lr   = lane >> 2;
    const int lc   = lane & 3;

    const int m0 = blockIdx.y * GBM;
    const int n0 = blockIdx.x * GBN;

    const int arow = t >> 1;
    const int acol = (t & 1) * 4;
    const int brow = t >> 5;
    const int bcol = (t & 31) * 4;

    const float* Ag = A + (size_t)(m0 + arow) * K + acol;
    const float* Bg = B + (size_t)brow * N + n0 + bcol;

    float acc[4][4][4];
#pragma unroll
    for (int i = 0; i < 4; i++)
#pragma unroll
        for (int j = 0; j < 4; j++)
#pragma unroll
            for (int r = 0; r < 4; r++) acc[i][j][r] = 0.0f;

    const int kTiles = K / GBK;

#pragma unroll
    for (int s = 0; s < 2; s++) {
        cp_async16(&As[s][arow][acol], Ag + (size_t)s * GBK);
        cp_async16(&Bs[s][brow][bcol], Bg + (size_t)s * GBK * N);
        cp_commit();
    }

    int p = 0;
    for (int kt = 0; kt < kTiles; kt++) {
        cp_wait<1>();
        __syncthreads();

        uint32_t afr[4][4];
        uint32_t bfr[4][2];
#pragma unroll
        for (int mf = 0; mf < 4; mf++) {
            const int m = wm * 64 + mf * 16 + lr;
            afr[mf][0] = __float_as_uint(As[p][m    ][lc]);
            afr[mf][1] = __float_as_uint(As[p][m + 8][lc]);
            afr[mf][2] = __float_as_uint(As[p][m    ][lc + 4]);
            afr[mf][3] = __float_as_uint(As[p][m + 8][lc + 4]);
        }
#pragma unroll
        for (int nf = 0; nf < 4; nf++) {
            const int n = wn * 32 + nf * 8 + lr;
            bfr[nf][0] = __float_as_uint(Bs[p][lc    ][n]);
            bfr[nf][1] = __float_as_uint(Bs[p][lc + 4][n]);
        }
#pragma unroll
        for (int mf = 0; mf < 4; mf++)
#pragma unroll
            for (int nf = 0; nf < 4; nf++)
                mma_tf32(acc[mf][nf], afr[mf], bfr[nf]);

        if (kt + 2 < kTiles) {
            const int s = (p + 2) % STAGES;
            const size_t ko = (size_t)(kt + 2) * GBK;
            cp_async16(&As[s][arow][acol], Ag + ko);
            cp_async16(&Bs[s][brow][bcol], Bg + ko * N);
        }
        cp_commit();

        p = (p + 1) % STAGES;
        __syncthreads();
    }

#pragma unroll
    for (int mf = 0; mf < 4; mf++) {
        const int r0 = m0 + wm * 64 + mf * 16 + lr;
#pragma unroll
        for (int nf = 0; nf < 4; nf++) {
            const int c0 = n0 + wn * 32 + nf * 8 + 2 * lc;
            const float b0 = bias[c0], b1 = bias[c0 + 1];
            float v0 = acc[mf][nf][0] + b0;
            float v1 = acc[mf][nf][1] + b1;
            float v2 = acc[mf][nf][2] + b0;
            float v3 = acc[mf][nf][3] + b1;
            if (ACT == 1) {
                v0 = gelu_exact(v0); v1 = gelu_exact(v1);
                v2 = gelu_exact(v2); v3 = gelu_exact(v3);
            }
            *(float2*)(C + (size_t)r0 * N + c0)       = make_float2(v0, v1);
            *(float2*)(C + (size_t)(r0 + 8) * N + c0) = make_float2(v2, v3);
        }
    }
}

// ---------------------------------------------------------------------------
// Tensor-core flash attention (TF32 mma), DK=64.
// NEW: cp.async double-buffered K/V tiles (2-deep ring, dynamic smem 70KB),
// ONE barrier per tile; K/V fed raw to mma (HW RZ truncation — attention
// error contribution measured negligible).
// ---------------------------------------------------------------------------
#define KS_STRIDE 68
#define VS_STRIDE 72
#define KS_ELEMS (64 * KS_STRIDE)
#define VS_ELEMS (64 * VS_STRIDE)
#define ATTN_SMEM ((2 * KS_ELEMS + 2 * VS_ELEMS) * 4)   // 71680 B

template<bool CAUSAL>
__global__ __launch_bounds__(256)
void flash_attn_tc(const float* __restrict__ Q, const float* __restrict__ K,
                   const float* __restrict__ V, float* __restrict__ O, int L)
{
    extern __shared__ float asmem[];
    // Ks(buf,row,col) = asmem[buf*KS_ELEMS + row*KS_STRIDE + col]
    // Vs(buf,row,col) = asmem[2*KS_ELEMS + buf*VS_ELEMS + row*VS_STRIDE + col]
    float* KsB = asmem;
    float* VsB = asmem + 2 * KS_ELEMS;

    const int t    = threadIdx.x;
    const int lane = t & 31;
    const int w    = t >> 5;
    const int lr   = lane >> 2;
    const int lc   = lane & 3;

    const int qt = blockIdx.x;
    const int bh = blockIdx.y;
    const int b  = bh >> 4;
    const int h  = bh & 15;
    const int q0 = qt * 128;
    const int wrow = q0 + w * 16;

    const float* Qb = Q + (size_t)(b * L) * D_MODEL + h * DK_;
    const float* Kb = K + (size_t)(b * L) * D_MODEL + h * DK_;
    const float* Vb = V + (size_t)(b * L) * D_MODEL + h * DK_;

    // load-tile mapping: 1024 16B-chunks per matrix, 4/thread
    int ldrow[4], ldc4[4];
#pragma unroll
    for (int i = 0; i < 4; i++) {
        const int idx = i * 256 + t;
        ldrow[i] = idx >> 4;
        ldc4[i]  = (idx & 15) * 4;
    }

    uint32_t qf[8][4];
    {
        const float* qr0 = Qb + (size_t)(wrow + lr) * D_MODEL;
        const float* qr1 = Qb + (size_t)(wrow + lr + 8) * D_MODEL;
#pragma unroll
        for (int kc = 0; kc < 8; kc++) {
            qf[kc][0] = to_tf32_bits(0.125f * qr0[8 * kc + lc]);
            qf[kc][1] = to_tf32_bits(0.125f * qr1[8 * kc + lc]);
            qf[kc][2] = to_tf32_bits(0.125f * qr0[8 * kc + lc + 4]);
            qf[kc][3] = to_tf32_bits(0.125f * qr1[8 * kc + lc + 4]);
        }
    }

    float o[8][4];
#pragma unroll
    for (int nf = 0; nf < 8; nf++)
#pragma unroll
        for (int i = 0; i < 4; i++) o[nf][i] = 0.0f;
    float m0r = -1e30f, m1r = -1e30f;
    float l0r = 0.0f,  l1r = 0.0f;

    const int ntile = CAUSAL ? (2 * qt + 2) : (L >> 6);

    // Prologue: async-load tile 0 into buffer 0
#pragma unroll
    for (int i = 0; i < 4; i++) {
        const size_t g = (size_t)ldrow[i] * D_MODEL + ldc4[i];
        cp_async16(&KsB[0 * KS_ELEMS + ldrow[i] * KS_STRIDE + ldc4[i]], Kb + g);
        cp_async16(&VsB[0 * VS_ELEMS + ldrow[i] * VS_STRIDE + ldc4[i]], Vb + g);
    }
    cp_commit();

    int p = 0;
    for (int kt = 0; kt < ntile; kt++) {
        cp_wait<0>();
        __syncthreads();   // tile kt visible; all warps done computing kt-1 (buffer p^1)

        // prefetch tile kt+1 into buffer p^1 (overlaps compute below)
        if (kt + 1 < ntile) {
            const int k0n = (kt + 1) * 64;
            const int q2 = p ^ 1;
#pragma unroll
            for (int i = 0; i < 4; i++) {
                const size_t g = (size_t)(k0n + ldrow[i]) * D_MODEL + ldc4[i];
                cp_async16(&KsB[q2 * KS_ELEMS + ldrow[i] * KS_STRIDE + ldc4[i]], Kb + g);
                cp_async16(&VsB[q2 * VS_ELEMS + ldrow[i] * VS_STRIDE + ldc4[i]], Vb + g);
            }
        }
        cp_commit();

        const int k0 = kt * 64;
        const bool active = (!CAUSAL) || (k0 <= wrow + 15);
        if (active) {
            const float* Ks = KsB + p * KS_ELEMS;
            const float* Vs = VsB + p * VS_ELEMS;

            float sacc[8][4];
#pragma unroll
            for (int nf = 0; nf < 8; nf++) {
                sacc[nf][0] = sacc[nf][1] = sacc[nf][2] = sacc[nf][3] = 0.0f;
#pragma unroll
                for (int kc = 0; kc < 8; kc++) {
                    uint32_t bfr[2];
                    bfr[0] = __float_as_uint(Ks[(8 * nf + lr) * KS_STRIDE + 8 * kc + lc]);
                    bfr[1] = __float_as_uint(Ks[(8 * nf + lr) * KS_STRIDE + 8 * kc + lc + 4]);
                    mma_tf32(sacc[nf], qf[kc], bfr);
                }
            }

            if (CAUSAL && (k0 + 63 > wrow)) {
                const int r0 = wrow + lr, r1 = wrow + lr + 8;
#pragma unroll
                for (int nf = 0; nf < 8; nf++) {
                    const int key = k0 + 8 * nf + 2 * lc;
                    if (key     > r0) sacc[nf][0] = -1e30f;
                    if (key + 1 > r0) sacc[nf][1] = -1e30f;
                    if (key     > r1) sacc[nf][2] = -1e30f;
                    if (key + 1 > r1) sacc[nf][3] = -1e30f;
                }
            }

            float mx0 = -1e30f, mx1 = -1e30f;
#pragma unroll
            for (int nf = 0; nf < 8; nf++) {
                mx0 = fmaxf(mx0, fmaxf(sacc[nf][0], sacc[nf][1]));
                mx1 = fmaxf(mx1, fmaxf(sacc[nf][2], sacc[nf][3]));
            }
            mx0 = fmaxf(mx0, __shfl_xor_sync(0xffffffffu, mx0, 1));
            mx0 = fmaxf(mx0, __shfl_xor_sync(0xffffffffu, mx0, 2));
            mx1 = fmaxf(mx1, __shfl_xor_sync(0xffffffffu, mx1, 1));
            mx1 = fmaxf(mx1, __shfl_xor_sync(0xffffffffu, mx1, 2));

            const float nm0 = fmaxf(m0r, mx0);
            const float nm1 = fmaxf(m1r, mx1);
            const float cr0 = __expf(m0r - nm0);
            const float cr1 = __expf(m1r - nm1);
            float sum0 = 0.f, sum1 = 0.f;
#pragma unroll
            for (int nf = 0; nf < 8; nf++) {
                sacc[nf][0] = __expf(sacc[nf][0] - nm0);
                sacc[nf][1] = __expf(sacc[nf][1] - nm0);
                sacc[nf][2] = __expf(sacc[nf][2] - nm1);
                sacc[nf][3] = __expf(sacc[nf][3] - nm1);
                sum0 += sacc[nf][0] + sacc[nf][1];
                sum1 += sacc[nf][2] + sacc[nf][3];
            }
            sum0 += __shfl_xor_sync(0xffffffffu, sum0, 1);
            sum0 += __shfl_xor_sync(0xffffffffu, sum0, 2);
            sum1 += __shfl_xor_sync(0xffffffffu, sum1, 1);
            sum1 += __shfl_xor_sync(0xffffffffu, sum1, 2);

            l0r = l0r * cr0 + sum0;
            l1r = l1r * cr1 + sum1;
            m0r = nm0; m1r = nm1;
#pragma unroll
            for (int nf = 0; nf < 8; nf++) {
                o[nf][0] *= cr0; o[nf][1] *= cr0;
                o[nf][2] *= cr1; o[nf][3] *= cr1;
            }

            const int qbase = lane & ~3;
            const int srcA  = qbase | (lc >> 1);
            const int srcB  = srcA + 2;
#pragma unroll
            for (int kc = 0; kc < 8; kc++) {
                const float p0a = __shfl_sync(0xffffffffu, sacc[kc][0], srcA);
                const float p1a = __shfl_sync(0xffffffffu, sacc[kc][1], srcA);
                const float p2a = __shfl_sync(0xffffffffu, sacc[kc][2], srcA);
                const float p3a = __shfl_sync(0xffffffffu, sacc[kc][3], srcA);
                const float p0b = __shfl_sync(0xffffffffu, sacc[kc][0], srcB);
                const float p1b = __shfl_sync(0xffffffffu, sacc[kc][1], srcB);
                const float p2b = __shfl_sync(0xffffffffu, sacc[kc][2], srcB);
                const float p3b = __shfl_sync(0xffffffffu, sacc[kc][3], srcB);
                uint32_t af[4];
                const bool odd = (lc & 1);
                af[0] = __float_as_uint(odd ? p1a : p0a);
                af[1] = __float_as_uint(odd ? p3a : p2a);
                af[2] = __float_as_uint(odd ? p1b : p0b);
                af[3] = __float_as_uint(odd ? p3b : p2b);
#pragma unroll
                for (int nf = 0; nf < 8; nf++) {
                    uint32_t bfr[2];
                    bfr[0] = __float_as_uint(Vs[(8 * kc + lc)     * VS_STRIDE + 8 * nf + lr]);
                    bfr[1] = __float_as_uint(Vs[(8 * kc + lc + 4) * VS_STRIDE + 8 * nf + lr]);
                    mma_tf32(o[nf], af, bfr);
                }
            }
        }
        p ^= 1;
    }

    const float inv0 = 1.0f / l0r;
    const float inv1 = 1.0f / l1r;
    float* O0 = O + (size_t)(b * L + wrow + lr) * D_MODEL + h * DK_;
    float* O1 = O + (size_t)(b * L + wrow + lr + 8) * D_MODEL + h * DK_;
#pragma unroll
    for (int nf = 0; nf < 8; nf++) {
        const int c = 8 * nf + 2 * lc;
        *(float2*)(O0 + c) = make_float2(o[nf][0] * inv0, o[nf][1] * inv0);
        *(float2*)(O1 + c) = make_float2(o[nf][2] * inv1, o[nf][3] * inv1);
    }
}

// ---------------------------------------------------------------------------
// Fused residual add + LayerNorm over last dim (1024). 1 block / row.
// ---------------------------------------------------------------------------
__global__ __launch_bounds__(128)
void add_layernorm(const float* __restrict__ A, const float* __restrict__ Bb,
                   const float* __restrict__ g, const float* __restrict__ be,
                   float* __restrict__ out)
{
    const int row = blockIdx.x;
    const int t = threadIdx.x;
    const float* a = A  + (size_t)row * D_MODEL;
    const float* b = Bb + (size_t)row * D_MODEL;

    float v[8];
    float s = 0.f, sq = 0.f;
#pragma unroll
    for (int i = 0; i < 8; i++) {
        const int c = t + i * 128;
        v[i] = a[c] + b[c];
        s += v[i];
        sq = fmaf(v[i], v[i], sq);
    }
#pragma unroll
    for (int o = 16; o > 0; o >>= 1) {
        s  += __shfl_down_sync(0xffffffffu, s,  o);
        sq += __shfl_down_sync(0xffffffffu, sq, o);
    }
    __shared__ float rs[4], rq[4];
    __shared__ float mean_s, rstd_s;
    const int w = t >> 5, ln = t & 31;
    if (ln == 0) { rs[w] = s; rq[w] = sq; }
    __syncthreads();
    if (t == 0) {
        const float S  = rs[0] + rs[1] + rs[2] + rs[3];
        const float Q2 = rq[0] + rq[1] + rq[2] + rq[3];
        const float mean = S * (1.0f / 1024.0f);
        const float var  = Q2 * (1.0f / 1024.0f) - mean * mean;
        mean_s = mean;
        rstd_s = rsqrtf(var + 1e-5f);
    }
    __syncthreads();
    const float mean = mean_s, rstd = rstd_s;
    float* op = out + (size_t)row * D_MODEL;
#pragma unroll
    for (int i = 0; i < 8; i++) {
        const int c = t + i * 128;
        op[c] = (v[i] - mean) * rstd * g[c] + be[c];
    }
}

// ---------------------------------------------------------------------------
// Host launcher
// ---------------------------------------------------------------------------
static float* devptr(const void* sym) {
    void* p = nullptr;
    cudaGetSymbolAddress(&p, sym);
    return (float*)p;
}

extern "C" void kernel_launch(void* const* d_in, const int* in_sizes, int n_in,
                              void* d_out, int out_size)
{
    const float* x   = (const float*)d_in[0];
    const float* enc = (const float*)d_in[1];
    const float* swq = (const float*)d_in[4];
    const float* sbq = (const float*)d_in[5];
    const float* swk = (const float*)d_in[6];
    const float* sbk = (const float*)d_in[7];
    const float* swv = (const float*)d_in[8];
    const float* sbv = (const float*)d_in[9];
    const float* swo = (const float*)d_in[10];
    const float* sbo = (const float*)d_in[11];
    const float* cwq = (const float*)d_in[12];
    const float* cbq = (const float*)d_in[13];
    const float* cwk = (const float*)d_in[14];
    const float* cbk = (const float*)d_in[15];
    const float* cwv = (const float*)d_in[16];
    const float* cbv = (const float*)d_in[17];
    const float* cwo = (const float*)d_in[18];
    const float* cbo = (const float*)d_in[19];
    const float* fw1 = (const float*)d_in[20];
    const float* fb1 = (const float*)d_in[21];
    const float* fw2 = (const float*)d_in[22];
    const float* fb2 = (const float*)d_in[23];
    const float* n1g = (const float*)d_in[24];
    const float* n1b = (const float*)d_in[25];
    const float* n2g = (const float*)d_in[26];
    const float* n2b = (const float*)d_in[27];
    const float* n3g = (const float*)d_in[28];
    const float* n3b = (const float*)d_in[29];
    float* out = (float*)d_out;

    float* q    = devptr(g_q);
    float* k    = devptr(g_k);
    float* v    = devptr(g_v);
    float* ctx  = devptr(g_ctx);
    float* proj = devptr(g_proj);
    float* x1   = devptr(g_x1);
    float* x2   = devptr(g_x2);
    float* ff   = devptr(g_ff);

    static bool attr_done = false;
    if (!attr_done) {
        cudaFuncSetAttribute(flash_attn_tc<true>,  cudaFuncAttributeMaxDynamicSharedMemorySize, ATTN_SMEM);
        cudaFuncSetAttribute(flash_attn_tc<false>, cudaFuncAttributeMaxDynamicSharedMemorySize, ATTN_SMEM);
        attr_done = true;
    }

    const int M = MROWS, Dm = D_MODEL, Dff = DFF_;
    dim3 blk(256);
    dim3 gP (Dm  / GBN, M / GBM);   // (8, 32)
    dim3 gF1(Dff / GBN, M / GBM);   // (32, 32)
    dim3 gA (SEQL / 128, 32);       // (16, B*H)

    // ---- self attention ----
    gemm_tf32<0><<<gP, blk>>>(x, swq, sbq, q, M, Dm, Dm);
    gemm_tf32<0><<<gP, blk>>>(x, swk, sbk, k, M, Dm, Dm);
    gemm_tf32<0><<<gP, blk>>>(x, swv, sbv, v, M, Dm, Dm);
    flash_attn_tc<true><<<gA, 256, ATTN_SMEM>>>(q, k, v, ctx, SEQL);
    gemm_tf32<0><<<gP, blk>>>(ctx, swo, sbo, proj, M, Dm, Dm);
    add_layernorm<<<M, 128>>>(x, proj, n1g, n1b, x1);

    // ---- cross attention ----
    gemm_tf32<0><<<gP, blk>>>(x1,  cwq, cbq, q, M, Dm, Dm);
    gemm_tf32<0><<<gP, blk>>>(enc, cwk, cbk, k, M, Dm, Dm);
    gemm_tf32<0><<<gP, blk>>>(enc, cwv, cbv, v, M, Dm, Dm);
    flash_attn_tc<false><<<gA, 256, ATTN_SMEM>>>(q, k, v, ctx, SEQL);
    gemm_tf32<0><<<gP, blk>>>(ctx, cwo, cbo, proj, M, Dm, Dm);
    add_layernorm<<<M, 128>>>(x1, proj, n2g, n2b, x2);

    // ---- feed-forward ----
    gemm_tf32<1><<<gF1, blk>>>(x2, fw1, fb1, ff, M, Dff, Dm);
    gemm_tf32<0><<<gP,  blk>>>(ff, fw2, fb2, proj, M, Dm, Dff);
    add_layernorm<<<M, 128>>>(x2, proj, n3g, n3b, out);
}